// round 2
// baseline (speedup 1.0000x reference)
#include <cuda_runtime.h>

#define WW 128
#define HH 128
#define NP 2048
#define DIMU 768
#define PTOT (HH*WW)

// ---- packed f32x2 helpers (sm_103a FFMA2) ----
__device__ __forceinline__ unsigned long long pk2(float lo, float hi) {
    unsigned long long v;
    asm("mov.b64 %0, {%1, %2};" : "=l"(v) : "f"(lo), "f"(hi));
    return v;
}
__device__ __forceinline__ unsigned long long ffma2(unsigned long long a,
                                                    unsigned long long b,
                                                    unsigned long long c) {
    unsigned long long d;
    asm("fma.rn.f32x2 %0, %1, %2, %3;" : "=l"(d) : "l"(a), "l"(b), "l"(c));
    return d;
}

// ============================================================
// Single fused kernel. Grid = 64 blocks (8x8 tiles of 16x16 px),
// 256 threads. Phases:
//   0) stage w_up/b_up into smem (float4 per dim)
//   1) 8 chunks of 256 gaussians: preprocess in-registers (fast
//      intrinsics), conservative bbox cull vs tile, deterministic
//      ballot-compact into smem, branch-free raster accumulate
//   2) clamp -> smem pixel arrays
//   3) up-projection: 8 px/thread x 8 dim-groups, f32x2 FFMA,
//      two STG.128 per (thread, dim)  -> HBM-write bound
// ============================================================
__global__ __launch_bounds__(256, 1) void k_fused(
    const float* __restrict__ xyz, const float* __restrict__ scaling,
    const float* __restrict__ rotation, const float* __restrict__ features,
    const float* __restrict__ opacity, const float* __restrict__ w_up,
    const float* __restrict__ b_up, float* __restrict__ out)
{
    __shared__ __align__(16) float4 swp[DIMU];   // wr, wg, wb, bias
    __shared__ __align__(16) float4 sA[256];     // gx, gy, 0.5A, B
    __shared__ __align__(16) float4 sB[256];     // 0.5C, op, cr, cg
    __shared__ __align__(16) float  scb[256];    // cb
    __shared__ __align__(16) float  sr[256], sg_[256], sbm[256];
    __shared__ int swc[8];

    const int tid  = threadIdx.x;
    const int lane = tid & 31;
    const int wid  = tid >> 5;

    // ---- phase 0: weights -> smem ----
    #pragma unroll
    for (int d = tid; d < DIMU; d += 256)
        swp[d] = make_float4(w_up[3*d+0], w_up[3*d+1], w_up[3*d+2], b_up[d]);

    // ---- tile geometry ----
    const int x0 = (blockIdx.x & 7) << 4;
    const int y0 = (blockIdx.x >> 3) << 4;
    const int tx = tid & 15, ty = tid >> 4;
    const float px = (float)(x0 + tx) + 0.5f;
    const float py = (float)(y0 + ty) + 0.5f;
    const float txmin = (float)x0 + 0.5f, txmax = (float)x0 + 15.5f;
    const float tymin = (float)y0 + 0.5f, tymax = (float)y0 + 15.5f;

    float accr = 0.0f, accg = 0.0f, accb = 0.0f;

    // ---- phase 1: chunked preprocess + cull + raster ----
    #pragma unroll 1
    for (int base = 0; base < NP; base += 256) {
        const int gi = base + tid;                       // NP % 256 == 0

        // preprocess (fast intrinsics)
        float e0 = __expf(2.0f * xyz[2*gi + 0]);
        float e1 = __expf(2.0f * xyz[2*gi + 1]);
        float gx = __fdividef(128.0f * e0, e0 + 1.0f);   // 0.5*(tanh+1)*W
        float gy = __fdividef(128.0f * e1, e1 + 1.0f);
        float s0 = fabsf(scaling[2*gi + 0] + 0.5f);
        float s1 = fabsf(scaling[2*gi + 1] + 0.5f);
        float th = 6.283185307179586f *
                   __fdividef(1.0f, 1.0f + __expf(-rotation[gi]));
        float sn, cs; __sincosf(th, &sn, &cs);
        float a = cs * s0, b = -sn * s1, dd = sn * s0, ee = cs * s1;
        float cxx = a*a + b*b;
        float cxy = a*dd + b*ee;
        float cyy = dd*dd + ee*ee;
        float det = cxx*cyy - cxy*cxy;
        float inv = __fdividef(1.0f, det);
        float hA =  0.5f * cyy * inv;
        float Bc = -cxy * inv;
        float hC =  0.5f * cxx * inv;
        float op = opacity[gi];
        float smax = __logf(255.0f * op);   // alpha>=1/255 <=> sigma<=smax

        bool keep = false;
        if (det > 0.0f && smax > 0.0f) {
            float rx = sqrtf(2.0f * smax * cxx) * 1.001f + 0.02f;
            float ry = sqrtf(2.0f * smax * cyy) * 1.001f + 0.02f;
            keep = (gx + rx >= txmin) && (gx - rx <= txmax) &&
                   (gy + ry >= tymin) && (gy - ry <= tymax);
        }

        // deterministic ballot compaction
        unsigned mask = __ballot_sync(0xffffffffu, keep);
        if (lane == 0) swc[wid] = __popc(mask);
        __syncthreads();
        int bp = 0, total = 0;
        #pragma unroll
        for (int w = 0; w < 8; w++) {
            int cw = swc[w];
            bp += (w < wid) ? cw : 0;
            total += cw;
        }
        if (keep) {
            int pos = bp + __popc(mask & ((1u << lane) - 1u));
            sA[pos]  = make_float4(gx, gy, hA, Bc);
            sB[pos]  = make_float4(hC, op, features[3*gi + 0], features[3*gi + 1]);
            scb[pos] = features[3*gi + 2];
        }
        __syncthreads();

        // raster accumulate
        #pragma unroll 2
        for (int j = 0; j < total; j++) {
            float4 a4 = sA[j];
            float4 b4 = sB[j];
            float  cb = scb[j];
            float dx = a4.x - px;
            float dy = a4.y - py;
            float sig = a4.z * dx * dx + a4.w * dx * dy + b4.x * dy * dy;
            float al = fminf(0.999f, b4.y * __expf(-sig));
            al = (sig >= 0.0f && al >= (1.0f / 255.0f)) ? al : 0.0f;
            accr = fmaf(al, b4.z, accr);
            accg = fmaf(al, b4.w, accg);
            accb = fmaf(al, cb,   accb);
        }
        __syncthreads();
    }

    // ---- phase 2: clamp -> pixel smem ----
    const int pidx = (ty << 4) | tx;
    sr[pidx]  = fminf(1.0f, fmaxf(0.0f, accr));
    sg_[pidx] = fminf(1.0f, fmaxf(0.0f, accg));
    sbm[pidx] = fminf(1.0f, fmaxf(0.0f, accb));
    __syncthreads();

    // ---- phase 3: up-projection + transposed store ----
    // lane -> 8 consecutive pixels (row = lane>>1, half = lane&1),
    // warp (=dg) -> dims d = i*8 + dg
    const int dg = wid;
    const int prow = lane >> 1;
    const int phalf = lane & 1;
    const int sbase = lane * 2;                    // float4 index into sr (lane*8 floats)

    const float4* sr4 = (const float4*)sr;
    const float4* sg4 = (const float4*)sg_;
    const float4* sb4 = (const float4*)sbm;
    float4 ra = sr4[sbase], rb = sr4[sbase + 1];
    float4 ga = sg4[sbase], gb = sg4[sbase + 1];
    float4 ba = sb4[sbase], bb4 = sb4[sbase + 1];

    unsigned long long r01 = pk2(ra.x, ra.y), r23 = pk2(ra.z, ra.w);
    unsigned long long r45 = pk2(rb.x, rb.y), r67 = pk2(rb.z, rb.w);
    unsigned long long g01 = pk2(ga.x, ga.y), g23 = pk2(ga.z, ga.w);
    unsigned long long g45 = pk2(gb.x, gb.y), g67 = pk2(gb.z, gb.w);
    unsigned long long b01 = pk2(ba.x, ba.y), b23 = pk2(ba.z, ba.w);
    unsigned long long b45 = pk2(bb4.x, bb4.y), b67 = pk2(bb4.z, bb4.w);

    float* p = out + (size_t)dg * PTOT
                   + (size_t)(y0 + prow) * WW + x0 + phalf * 8;

    #pragma unroll 4
    for (int i = 0; i < DIMU / 8; i++) {
        float4 w = swp[(i << 3) + dg];
        unsigned long long wr = pk2(w.x, w.x);
        unsigned long long wg = pk2(w.y, w.y);
        unsigned long long wb = pk2(w.z, w.z);
        unsigned long long bd = pk2(w.w, w.w);

        unsigned long long o01 = ffma2(b01, wb, ffma2(g01, wg, ffma2(r01, wr, bd)));
        unsigned long long o23 = ffma2(b23, wb, ffma2(g23, wg, ffma2(r23, wr, bd)));
        unsigned long long o45 = ffma2(b45, wb, ffma2(g45, wg, ffma2(r45, wr, bd)));
        unsigned long long o67 = ffma2(b67, wb, ffma2(g67, wg, ffma2(r67, wr, bd)));

        ulonglong2 v0; v0.x = o01; v0.y = o23;
        ulonglong2 v1; v1.x = o45; v1.y = o67;
        *(ulonglong2*)(p)     = v0;
        *(ulonglong2*)(p + 4) = v1;
        p += 8 * PTOT;
    }
}

// ============================================================
extern "C" void kernel_launch(void* const* d_in, const int* in_sizes, int n_in,
                              void* d_out, int out_size) {
    // metadata order: x, xyz, scaling, rotation, features, opacity, w_up, b_up
    const float* xyz      = (const float*)d_in[1];
    const float* scaling  = (const float*)d_in[2];
    const float* rotation = (const float*)d_in[3];
    const float* features = (const float*)d_in[4];
    const float* opacity  = (const float*)d_in[5];
    const float* w_up     = (const float*)d_in[6];
    const float* b_up     = (const float*)d_in[7];
    float* out = (float*)d_out;

    k_fused<<<64, 256>>>(xyz, scaling, rotation, features, opacity,
                         w_up, b_up, out);
}

// round 3
// speedup vs baseline: 1.6933x; 1.6933x over previous
#include <cuda_runtime.h>

#define WW 128
#define HH 128
#define NP 2048
#define DIMU 768
#define PTOT (HH*WW)

// ---- scratch (device globals: no allocation allowed) ----
__device__ __align__(16) float4 g_pA[NP];   // gx, gy, rx, ry   (rx<0 => culled)
__device__ __align__(16) float4 g_pB[NP];   // 0.5A, B, 0.5C, opacity
__device__ __align__(16) float4 g_pC[NP];   // cr, cg, cb, pad
__device__ __align__(16) float  g_imr[PTOT];
__device__ __align__(16) float  g_img[PTOT];
__device__ __align__(16) float  g_imb[PTOT];

// ============================================================
// K1: per-gaussian preprocess (N=2048), fast intrinsics (MUFU)
// ============================================================
__global__ void k_pre(const float* __restrict__ xyz,
                      const float* __restrict__ scaling,
                      const float* __restrict__ rotation,
                      const float* __restrict__ features,
                      const float* __restrict__ opacity) {
    int n = blockIdx.x * blockDim.x + threadIdx.x;
    if (n >= NP) return;

    float e0 = __expf(2.0f * xyz[2*n + 0]);
    float e1 = __expf(2.0f * xyz[2*n + 1]);
    float gx = __fdividef(128.0f * e0, e0 + 1.0f);   // 0.5*(tanh+1)*W
    float gy = __fdividef(128.0f * e1, e1 + 1.0f);
    float s0 = fabsf(scaling[2*n + 0] + 0.5f);
    float s1 = fabsf(scaling[2*n + 1] + 0.5f);
    float th = 6.283185307179586f *
               __fdividef(1.0f, 1.0f + __expf(-rotation[n]));
    float sn, cs; __sincosf(th, &sn, &cs);
    float a = cs * s0, b = -sn * s1, dd = sn * s0, ee = cs * s1;
    float cxx = a*a + b*b;
    float cxy = a*dd + b*ee;
    float cyy = dd*dd + ee*ee;
    float det = cxx*cyy - cxy*cxy;
    float inv = __fdividef(1.0f, det);
    float hA =  0.5f * cyy * inv;
    float Bc = -cxy * inv;
    float hC =  0.5f * cxx * inv;
    float op = opacity[n];
    float smax = __logf(255.0f * op);   // alpha>=1/255 <=> sigma<=smax

    float rx, ry;
    if (det > 0.0f && smax > 0.0f) {
        rx = sqrtf(2.0f * smax * cxx) * 1.001f + 0.02f;
        ry = sqrtf(2.0f * smax * cyy) * 1.001f + 0.02f;
    } else {
        rx = -1.0f; ry = -1.0f;
    }
    g_pA[n] = make_float4(gx, gy, rx, ry);
    g_pB[n] = make_float4(hA, Bc, hC, op);
    g_pC[n] = make_float4(features[3*n+0], features[3*n+1], features[3*n+2], 0.0f);
}

// ============================================================
// K2: tiled rasterizer. 16x16 pixel tile per block, 256 thr.
// Chunked cull+compact into smem, then branch-free accumulate.
// ============================================================
__global__ void k_raster() {
    __shared__ float4 sA[256];
    __shared__ float4 sB[256];
    __shared__ float4 sC[256];
    __shared__ int s_cnt;

    int tid = threadIdx.x;
    int tx = tid & 15, ty = tid >> 4;
    int x0 = blockIdx.x * 16, y0 = blockIdx.y * 16;
    float px = (float)(x0 + tx) + 0.5f;
    float py = (float)(y0 + ty) + 0.5f;
    float txmin = (float)x0 + 0.5f, txmax = (float)x0 + 15.5f;
    float tymin = (float)y0 + 0.5f, tymax = (float)y0 + 15.5f;

    float accr = 0.0f, accg = 0.0f, accb = 0.0f;

    #pragma unroll 1
    for (int base = 0; base < NP; base += 256) {
        if (tid == 0) s_cnt = 0;
        __syncthreads();
        int gi = base + tid;                    // NP % 256 == 0
        float4 a = g_pA[gi];
        if (a.z >= 0.0f &&
            a.x + a.z >= txmin && a.x - a.z <= txmax &&
            a.y + a.w >= tymin && a.y - a.w <= tymax) {
            int pos = atomicAdd(&s_cnt, 1);
            sA[pos] = a;
            sB[pos] = g_pB[gi];
            sC[pos] = g_pC[gi];
        }
        __syncthreads();
        int cnt = s_cnt;
        for (int j = 0; j < cnt; j++) {
            float4 pa = sA[j];
            float4 pb = sB[j];
            float4 pc = sC[j];
            float dx = pa.x - px;
            float dy = pa.y - py;
            float sig = pb.x * dx * dx + pb.z * dy * dy + pb.y * dx * dy;
            float al = fminf(0.999f, pb.w * __expf(-sig));
            al = (sig >= 0.0f && al >= (1.0f / 255.0f)) ? al : 0.0f;
            accr = fmaf(al, pc.x, accr);
            accg = fmaf(al, pc.y, accg);
            accb = fmaf(al, pc.z, accb);
        }
        __syncthreads();
    }

    int p = (y0 + ty) * WW + (x0 + tx);
    g_imr[p] = fminf(1.0f, fmaxf(0.0f, accr));
    g_img[p] = fminf(1.0f, fmaxf(0.0f, accg));
    g_imb[p] = fminf(1.0f, fmaxf(0.0f, accb));
}

// ============================================================
// K3: up-projection + transposed write.
// Block = (1024 pixels) x (16 output dims). Weights staged in
// smem once. 768 blocks -> stores spread across all SMs.
// ============================================================
#define D_BLK 16
__global__ __launch_bounds__(256) void k_up(const float* __restrict__ w_up,
                                            const float* __restrict__ b_up,
                                            float* __restrict__ out) {
    __shared__ __align__(16) float4 sw[D_BLK];   // wr, wg, wb, bias

    int tid = threadIdx.x;                         // 256
    int db  = blockIdx.y * D_BLK;
    if (tid < D_BLK) {
        int d = db + tid;
        sw[tid] = make_float4(w_up[3*d + 0], w_up[3*d + 1], w_up[3*d + 2],
                              b_up[d]);
    }
    int p4 = blockIdx.x * 256 + tid;               // float4 pixel index
    float4 R = ((const float4*)g_imr)[p4];
    float4 G = ((const float4*)g_img)[p4];
    float4 B = ((const float4*)g_imb)[p4];
    __syncthreads();

    float4* out4 = (float4*)out;
    #pragma unroll
    for (int i = 0; i < D_BLK; i++) {
        float4 w = sw[i];
        float4 o;
        o.x = fmaf(B.x, w.z, fmaf(G.x, w.y, fmaf(R.x, w.x, w.w)));
        o.y = fmaf(B.y, w.z, fmaf(G.y, w.y, fmaf(R.y, w.x, w.w)));
        o.z = fmaf(B.z, w.z, fmaf(G.z, w.y, fmaf(R.z, w.x, w.w)));
        o.w = fmaf(B.w, w.z, fmaf(G.w, w.y, fmaf(R.w, w.x, w.w)));
        out4[(size_t)(db + i) * (PTOT / 4) + p4] = o;
    }
}

// ============================================================
extern "C" void kernel_launch(void* const* d_in, const int* in_sizes, int n_in,
                              void* d_out, int out_size) {
    // metadata order: x, xyz, scaling, rotation, features, opacity, w_up, b_up
    const float* xyz      = (const float*)d_in[1];
    const float* scaling  = (const float*)d_in[2];
    const float* rotation = (const float*)d_in[3];
    const float* features = (const float*)d_in[4];
    const float* opacity  = (const float*)d_in[5];
    const float* w_up     = (const float*)d_in[6];
    const float* b_up     = (const float*)d_in[7];
    float* out = (float*)d_out;

    k_pre<<<(NP + 255) / 256, 256>>>(xyz, scaling, rotation, features, opacity);
    k_raster<<<dim3(WW / 16, HH / 16), 256>>>();
    k_up<<<dim3(PTOT / 1024, DIMU / D_BLK), 256>>>(w_up, b_up, out);
}

// round 4
// speedup vs baseline: 1.7169x; 1.0139x over previous
#include <cuda_runtime.h>

#define WW 128
#define HH 128
#define NP 2048
#define DIMU 768
#define PTOT (HH*WW)

// ---- scratch (device globals: no allocation allowed) ----
__device__ __align__(16) float g_imr[PTOT];
__device__ __align__(16) float g_img[PTOT];
__device__ __align__(16) float g_imb[PTOT];

// ============================================================
// K1: fused preprocess + tiled rasterizer.
// 64 blocks (8x8 tiles of 16x16 px), 256 threads.
// Each chunk of 256 gaussians is preprocessed in-registers
// (fast MUFU intrinsics), bbox-culled vs the tile, ballot-
// compacted into smem (deterministic), then accumulated.
// ============================================================
__global__ __launch_bounds__(256, 1) void k_praster(
    const float* __restrict__ xyz, const float* __restrict__ scaling,
    const float* __restrict__ rotation, const float* __restrict__ features,
    const float* __restrict__ opacity)
{
    __shared__ __align__(16) float4 sA[256];     // gx, gy, 0.5A, B
    __shared__ __align__(16) float4 sB[256];     // 0.5C, op, cr, cg
    __shared__ __align__(16) float  scb[256];    // cb
    __shared__ int swc[8];

    const int tid  = threadIdx.x;
    const int lane = tid & 31;
    const int wid  = tid >> 5;

    const int x0 = (blockIdx.x & 7) << 4;
    const int y0 = (blockIdx.x >> 3) << 4;
    const int tx = tid & 15, ty = tid >> 4;
    const float px = (float)(x0 + tx) + 0.5f;
    const float py = (float)(y0 + ty) + 0.5f;
    const float txmin = (float)x0 + 0.5f, txmax = (float)x0 + 15.5f;
    const float tymin = (float)y0 + 0.5f, tymax = (float)y0 + 15.5f;

    float accr = 0.0f, accg = 0.0f, accb = 0.0f;

    #pragma unroll 1
    for (int base = 0; base < NP; base += 256) {
        const int gi = base + tid;                       // NP % 256 == 0

        // ---- preprocess (fast intrinsics) ----
        float2 xy = ((const float2*)xyz)[gi];
        float2 sc = ((const float2*)scaling)[gi];
        float e0 = __expf(2.0f * xy.x);
        float e1 = __expf(2.0f * xy.y);
        float gx = __fdividef(128.0f * e0, e0 + 1.0f);   // 0.5*(tanh+1)*W
        float gy = __fdividef(128.0f * e1, e1 + 1.0f);
        float s0 = fabsf(sc.x + 0.5f);
        float s1 = fabsf(sc.y + 0.5f);
        float th = 6.283185307179586f *
                   __fdividef(1.0f, 1.0f + __expf(-rotation[gi]));
        float sn, cs; __sincosf(th, &sn, &cs);
        float a = cs * s0, b = -sn * s1, dd = sn * s0, ee = cs * s1;
        float cxx = a*a + b*b;
        float cxy = a*dd + b*ee;
        float cyy = dd*dd + ee*ee;
        float det = cxx*cyy - cxy*cxy;
        float inv = __fdividef(1.0f, det);
        float hA =  0.5f * cyy * inv;
        float Bc = -cxy * inv;
        float hC =  0.5f * cxx * inv;
        float op = opacity[gi];
        float smax = __logf(255.0f * op);   // alpha>=1/255 <=> sigma<=smax

        bool keep = false;
        if (det > 0.0f && smax > 0.0f) {
            float rx = sqrtf(2.0f * smax * cxx) * 1.001f + 0.02f;
            float ry = sqrtf(2.0f * smax * cyy) * 1.001f + 0.02f;
            keep = (gx + rx >= txmin) && (gx - rx <= txmax) &&
                   (gy + ry >= tymin) && (gy - ry <= tymax);
        }

        // ---- deterministic ballot compaction ----
        unsigned mask = __ballot_sync(0xffffffffu, keep);
        if (lane == 0) swc[wid] = __popc(mask);
        __syncthreads();
        int bp = 0, total = 0;
        #pragma unroll
        for (int w = 0; w < 8; w++) {
            int cw = swc[w];
            bp += (w < wid) ? cw : 0;
            total += cw;
        }
        if (keep) {
            int pos = bp + __popc(mask & ((1u << lane) - 1u));
            sA[pos]  = make_float4(gx, gy, hA, Bc);
            sB[pos]  = make_float4(hC, op, features[3*gi + 0], features[3*gi + 1]);
            scb[pos] = features[3*gi + 2];
        }
        __syncthreads();

        // ---- raster accumulate ----
        #pragma unroll 2
        for (int j = 0; j < total; j++) {
            float4 a4 = sA[j];
            float4 b4 = sB[j];
            float  cb = scb[j];
            float dx = a4.x - px;
            float dy = a4.y - py;
            float sig = a4.z * dx * dx + a4.w * dx * dy + b4.x * dy * dy;
            float al = fminf(0.999f, b4.y * __expf(-sig));
            al = (sig >= 0.0f && al >= (1.0f / 255.0f)) ? al : 0.0f;
            accr = fmaf(al, b4.z, accr);
            accg = fmaf(al, b4.w, accg);
            accb = fmaf(al, cb,   accb);
        }
        __syncthreads();
    }

    const int p = (y0 + ty) * WW + (x0 + tx);
    g_imr[p] = fminf(1.0f, fmaxf(0.0f, accr));
    g_img[p] = fminf(1.0f, fmaxf(0.0f, accg));
    g_imb[p] = fminf(1.0f, fmaxf(0.0f, accb));
}

// ============================================================
// K2: up-projection + transposed write.
// Block = (1024 pixels) x (32 output dims). Weights staged in
// smem once. 384 blocks -> stores spread across all SMs.
// ============================================================
#define D_BLK 32
__global__ __launch_bounds__(256) void k_up(const float* __restrict__ w_up,
                                            const float* __restrict__ b_up,
                                            float* __restrict__ out) {
    __shared__ __align__(16) float4 sw[D_BLK];   // wr, wg, wb, bias

    int tid = threadIdx.x;                         // 256
    int db  = blockIdx.y * D_BLK;
    if (tid < D_BLK) {
        int d = db + tid;
        sw[tid] = make_float4(w_up[3*d + 0], w_up[3*d + 1], w_up[3*d + 2],
                              b_up[d]);
    }
    int p4 = blockIdx.x * 256 + tid;               // float4 pixel index
    float4 R = ((const float4*)g_imr)[p4];
    float4 G = ((const float4*)g_img)[p4];
    float4 B = ((const float4*)g_imb)[p4];
    __syncthreads();

    float4* out4 = (float4*)out;
    #pragma unroll 8
    for (int i = 0; i < D_BLK; i++) {
        float4 w = sw[i];
        float4 o;
        o.x = fmaf(B.x, w.z, fmaf(G.x, w.y, fmaf(R.x, w.x, w.w)));
        o.y = fmaf(B.y, w.z, fmaf(G.y, w.y, fmaf(R.y, w.x, w.w)));
        o.z = fmaf(B.z, w.z, fmaf(G.z, w.y, fmaf(R.z, w.x, w.w)));
        o.w = fmaf(B.w, w.z, fmaf(G.w, w.y, fmaf(R.w, w.x, w.w)));
        out4[(size_t)(db + i) * (PTOT / 4) + p4] = o;
    }
}

// ============================================================
extern "C" void kernel_launch(void* const* d_in, const int* in_sizes, int n_in,
                              void* d_out, int out_size) {
    // metadata order: x, xyz, scaling, rotation, features, opacity, w_up, b_up
    const float* xyz      = (const float*)d_in[1];
    const float* scaling  = (const float*)d_in[2];
    const float* rotation = (const float*)d_in[3];
    const float* features = (const float*)d_in[4];
    const float* opacity  = (const float*)d_in[5];
    const float* w_up     = (const float*)d_in[6];
    const float* b_up     = (const float*)d_in[7];
    float* out = (float*)d_out;

    k_praster<<<64, 256>>>(xyz, scaling, rotation, features, opacity);
    k_up<<<dim3(PTOT / 1024, DIMU / D_BLK), 256>>>(w_up, b_up, out);
}

// round 5
// speedup vs baseline: 1.8511x; 1.0782x over previous
#include <cuda_runtime.h>

#define WW 128
#define HH 128
#define NP 2048
#define DIMU 768
#define PTOT (HH*WW)

// ---- scratch (device globals: no allocation allowed) ----
__device__ __align__(16) float g_imr[PTOT];
__device__ __align__(16) float g_img[PTOT];
__device__ __align__(16) float g_imb[PTOT];

// ---- packed f32x2 helpers (sm_103a FFMA2) ----
__device__ __forceinline__ unsigned long long pk2(float lo, float hi) {
    unsigned long long v;
    asm("mov.b64 %0, {%1, %2};" : "=l"(v) : "f"(lo), "f"(hi));
    return v;
}
__device__ __forceinline__ unsigned long long ffma2(unsigned long long a,
                                                    unsigned long long b,
                                                    unsigned long long c) {
    unsigned long long d;
    asm("fma.rn.f32x2 %0, %1, %2, %3;" : "=l"(d) : "l"(a), "l"(b), "l"(c));
    return d;
}

// ============================================================
// K1: fused preprocess + tiled rasterizer.
// 64 blocks (8x8 tiles of 16x16 px), 256 threads.
// Depth-2 prefetch of gaussian inputs hides LDG latency behind
// the previous chunk's preprocess + raster work.
// ============================================================
__global__ __launch_bounds__(256, 1) void k_praster(
    const float* __restrict__ xyz, const float* __restrict__ scaling,
    const float* __restrict__ rotation, const float* __restrict__ features,
    const float* __restrict__ opacity)
{
    __shared__ __align__(16) float4 sA[256];     // gx, gy, 0.5A, B
    __shared__ __align__(16) float4 sB[256];     // 0.5C, op, cr, cg
    __shared__ __align__(16) float  scb[256];    // cb
    __shared__ int swc[8];

    const int tid  = threadIdx.x;
    const int lane = tid & 31;
    const int wid  = tid >> 5;

    const int x0 = (blockIdx.x & 7) << 4;
    const int y0 = (blockIdx.x >> 3) << 4;
    const int tx = tid & 15, ty = tid >> 4;
    const float px = (float)(x0 + tx) + 0.5f;
    const float py = (float)(y0 + ty) + 0.5f;
    const float txmin = (float)x0 + 0.5f, txmax = (float)x0 + 15.5f;
    const float tymin = (float)y0 + 0.5f, tymax = (float)y0 + 15.5f;

    float accr = 0.0f, accg = 0.0f, accb = 0.0f;

    // ---- prefetch chunk 0 ----
    float2 nxy = ((const float2*)xyz)[tid];
    float2 nsc = ((const float2*)scaling)[tid];
    float  nrt = rotation[tid];
    float  nop = opacity[tid];
    float  nf0 = features[3*tid + 0];
    float  nf1 = features[3*tid + 1];
    float  nf2 = features[3*tid + 2];

    #pragma unroll 1
    for (int base = 0; base < NP; base += 256) {
        // consume prefetched, issue next chunk's loads
        float2 xy = nxy; float2 sc = nsc;
        float rt = nrt, op = nop, f0 = nf0, f1 = nf1, f2 = nf2;
        if (base + 256 < NP) {
            const int ngi = base + 256 + tid;
            nxy = ((const float2*)xyz)[ngi];
            nsc = ((const float2*)scaling)[ngi];
            nrt = rotation[ngi];
            nop = opacity[ngi];
            nf0 = features[3*ngi + 0];
            nf1 = features[3*ngi + 1];
            nf2 = features[3*ngi + 2];
        }

        // ---- preprocess (fast intrinsics) ----
        float e0 = __expf(2.0f * xy.x);
        float e1 = __expf(2.0f * xy.y);
        float gx = __fdividef(128.0f * e0, e0 + 1.0f);   // 0.5*(tanh+1)*W
        float gy = __fdividef(128.0f * e1, e1 + 1.0f);
        float s0 = fabsf(sc.x + 0.5f);
        float s1 = fabsf(sc.y + 0.5f);
        float th = 6.283185307179586f *
                   __fdividef(1.0f, 1.0f + __expf(-rt));
        float sn, cs; __sincosf(th, &sn, &cs);
        float a = cs * s0, b = -sn * s1, dd = sn * s0, ee = cs * s1;
        float cxx = a*a + b*b;
        float cxy = a*dd + b*ee;
        float cyy = dd*dd + ee*ee;
        float det = cxx*cyy - cxy*cxy;
        float inv = __fdividef(1.0f, det);
        float hA =  0.5f * cyy * inv;
        float Bc = -cxy * inv;
        float hC =  0.5f * cxx * inv;
        float smax = __logf(255.0f * op);   // alpha>=1/255 <=> sigma<=smax

        bool keep = false;
        if (det > 0.0f && smax > 0.0f) {
            float rx = sqrtf(2.0f * smax * cxx) * 1.001f + 0.02f;
            float ry = sqrtf(2.0f * smax * cyy) * 1.001f + 0.02f;
            keep = (gx + rx >= txmin) && (gx - rx <= txmax) &&
                   (gy + ry >= tymin) && (gy - ry <= tymax);
        }

        // ---- deterministic ballot compaction ----
        unsigned mask = __ballot_sync(0xffffffffu, keep);
        if (lane == 0) swc[wid] = __popc(mask);
        __syncthreads();
        int bp = 0, total = 0;
        #pragma unroll
        for (int w = 0; w < 8; w++) {
            int cw = swc[w];
            bp += (w < wid) ? cw : 0;
            total += cw;
        }
        if (keep) {
            int pos = bp + __popc(mask & ((1u << lane) - 1u));
            sA[pos]  = make_float4(gx, gy, hA, Bc);
            sB[pos]  = make_float4(hC, op, f0, f1);
            scb[pos] = f2;
        }
        __syncthreads();

        // ---- raster accumulate ----
        #pragma unroll 2
        for (int j = 0; j < total; j++) {
            float4 a4 = sA[j];
            float4 b4 = sB[j];
            float  cb = scb[j];
            float dx = a4.x - px;
            float dy = a4.y - py;
            float sig = a4.z * dx * dx + a4.w * dx * dy + b4.x * dy * dy;
            float al = fminf(0.999f, b4.y * __expf(-sig));
            al = (sig >= 0.0f && al >= (1.0f / 255.0f)) ? al : 0.0f;
            accr = fmaf(al, b4.z, accr);
            accg = fmaf(al, b4.w, accg);
            accb = fmaf(al, cb,   accb);
        }
        __syncthreads();
    }

    const int p = (y0 + ty) * WW + (x0 + tx);
    g_imr[p] = fminf(1.0f, fmaxf(0.0f, accr));
    g_img[p] = fminf(1.0f, fmaxf(0.0f, accg));
    g_imb[p] = fminf(1.0f, fmaxf(0.0f, accb));
}

// ============================================================
// K2: up-projection + transposed write, f32x2 packed math.
// Block = (1024 px) x (16 dims); 768 blocks (5.2/SM).
// Per (thread, dim): 2 LDS.128 + 6 FFMA2 + 1 STG.128.
// ============================================================
#define D_BLK 16
__global__ __launch_bounds__(256) void k_up(const float* __restrict__ w_up,
                                            const float* __restrict__ b_up,
                                            float* __restrict__ out) {
    // pre-packed duplicated weights: [d][0]={wr2,wg2}, [d][1]={wb2,bias2}
    __shared__ __align__(16) ulonglong2 sw2[D_BLK][2];

    const int tid = threadIdx.x;                   // 256
    const int db  = blockIdx.y * D_BLK;
    if (tid < D_BLK) {
        int d = db + tid;
        float wr = w_up[3*d + 0], wg = w_up[3*d + 1], wb = w_up[3*d + 2];
        float bi = b_up[d];
        ulonglong2 a; a.x = pk2(wr, wr); a.y = pk2(wg, wg);
        ulonglong2 b; b.x = pk2(wb, wb); b.y = pk2(bi, bi);
        sw2[tid][0] = a;
        sw2[tid][1] = b;
    }

    const int p4 = blockIdx.x * 256 + tid;         // float4 pixel index
    float4 R = ((const float4*)g_imr)[p4];
    float4 G = ((const float4*)g_img)[p4];
    float4 B = ((const float4*)g_imb)[p4];
    unsigned long long r01 = pk2(R.x, R.y), r23 = pk2(R.z, R.w);
    unsigned long long g01 = pk2(G.x, G.y), g23 = pk2(G.z, G.w);
    unsigned long long b01 = pk2(B.x, B.y), b23 = pk2(B.z, B.w);
    __syncthreads();

    float* outp = out + (size_t)db * PTOT + (size_t)p4 * 4;
    #pragma unroll
    for (int i = 0; i < D_BLK; i++) {
        ulonglong2 wa = sw2[i][0];     // {wr2, wg2}
        ulonglong2 wb = sw2[i][1];     // {wb2, bias2}
        ulonglong2 v;
        v.x = ffma2(b01, wb.x, ffma2(g01, wa.y, ffma2(r01, wa.x, wb.y)));
        v.y = ffma2(b23, wb.x, ffma2(g23, wa.y, ffma2(r23, wa.x, wb.y)));
        *(ulonglong2*)outp = v;
        outp += PTOT;
    }
}

// ============================================================
extern "C" void kernel_launch(void* const* d_in, const int* in_sizes, int n_in,
                              void* d_out, int out_size) {
    // metadata order: x, xyz, scaling, rotation, features, opacity, w_up, b_up
    const float* xyz      = (const float*)d_in[1];
    const float* scaling  = (const float*)d_in[2];
    const float* rotation = (const float*)d_in[3];
    const float* features = (const float*)d_in[4];
    const float* opacity  = (const float*)d_in[5];
    const float* w_up     = (const float*)d_in[6];
    const float* b_up     = (const float*)d_in[7];
    float* out = (float*)d_out;

    k_praster<<<64, 256>>>(xyz, scaling, rotation, features, opacity);
    k_up<<<dim3(PTOT / 1024, DIMU / D_BLK), 256>>>(w_up, b_up, out);
}

// round 6
// speedup vs baseline: 1.8765x; 1.0137x over previous
#include <cuda_runtime.h>

#define WW 128
#define HH 128
#define NP 2048
#define DIMU 768
#define PTOT (HH*WW)

// ---- scratch (device globals: no allocation allowed) ----
__device__ __align__(16) float g_imr[PTOT];
__device__ __align__(16) float g_img[PTOT];
__device__ __align__(16) float g_imb[PTOT];

// ---- packed f32x2 helpers (sm_103a FFMA2) ----
__device__ __forceinline__ unsigned long long pk2(float lo, float hi) {
    unsigned long long v;
    asm("mov.b64 %0, {%1, %2};" : "=l"(v) : "f"(lo), "f"(hi));
    return v;
}
__device__ __forceinline__ unsigned long long ffma2(unsigned long long a,
                                                    unsigned long long b,
                                                    unsigned long long c) {
    unsigned long long d;
    asm("fma.rn.f32x2 %0, %1, %2, %3;" : "=l"(d) : "l"(a), "l"(b), "l"(c));
    return d;
}

// ============================================================
// K1: fused preprocess + tiled rasterizer.
// 64 blocks (8x8 tiles of 16x16 px), 256 threads.
// Depth-2 input prefetch + double-buffered compaction smem
// (2 barriers per chunk instead of 3).
// ============================================================
__global__ __launch_bounds__(256, 1) void k_praster(
    const float* __restrict__ xyz, const float* __restrict__ scaling,
    const float* __restrict__ rotation, const float* __restrict__ features,
    const float* __restrict__ opacity)
{
    __shared__ __align__(16) float4 sA[2][256];   // gx, gy, 0.5A, B
    __shared__ __align__(16) float4 sB[2][256];   // 0.5C, op, cr, cg
    __shared__ __align__(16) float  scb[2][256];  // cb
    __shared__ int swc[2][8];

    const int tid  = threadIdx.x;
    const int lane = tid & 31;
    const int wid  = tid >> 5;

    const int x0 = (blockIdx.x & 7) << 4;
    const int y0 = (blockIdx.x >> 3) << 4;
    const int tx = tid & 15, ty = tid >> 4;
    const float px = (float)(x0 + tx) + 0.5f;
    const float py = (float)(y0 + ty) + 0.5f;
    const float txmin = (float)x0 + 0.5f, txmax = (float)x0 + 15.5f;
    const float tymin = (float)y0 + 0.5f, tymax = (float)y0 + 15.5f;

    float accr = 0.0f, accg = 0.0f, accb = 0.0f;

    // ---- prefetch chunk 0 ----
    float2 nxy = ((const float2*)xyz)[tid];
    float2 nsc = ((const float2*)scaling)[tid];
    float  nrt = rotation[tid];
    float  nop = opacity[tid];
    float  nf0 = features[3*tid + 0];
    float  nf1 = features[3*tid + 1];
    float  nf2 = features[3*tid + 2];

    #pragma unroll 1
    for (int ck = 0; ck < NP / 256; ck++) {
        const int c = ck & 1;
        // consume prefetched, issue next chunk's loads
        float2 xy = nxy; float2 sc = nsc;
        float rt = nrt, op = nop, f0 = nf0, f1 = nf1, f2 = nf2;
        if (ck + 1 < NP / 256) {
            const int ngi = (ck + 1) * 256 + tid;
            nxy = ((const float2*)xyz)[ngi];
            nsc = ((const float2*)scaling)[ngi];
            nrt = rotation[ngi];
            nop = opacity[ngi];
            nf0 = features[3*ngi + 0];
            nf1 = features[3*ngi + 1];
            nf2 = features[3*ngi + 2];
        }

        // ---- preprocess (fast intrinsics) ----
        float e0 = __expf(2.0f * xy.x);
        float e1 = __expf(2.0f * xy.y);
        float gx = __fdividef(128.0f * e0, e0 + 1.0f);   // 0.5*(tanh+1)*W
        float gy = __fdividef(128.0f * e1, e1 + 1.0f);
        float s0 = fabsf(sc.x + 0.5f);
        float s1 = fabsf(sc.y + 0.5f);
        float th = 6.283185307179586f *
                   __fdividef(1.0f, 1.0f + __expf(-rt));
        float sn, cs; __sincosf(th, &sn, &cs);
        float a = cs * s0, b = -sn * s1, dd = sn * s0, ee = cs * s1;
        float cxx = a*a + b*b;
        float cxy = a*dd + b*ee;
        float cyy = dd*dd + ee*ee;
        float det = cxx*cyy - cxy*cxy;
        float inv = __fdividef(1.0f, det);
        float hA =  0.5f * cyy * inv;
        float Bc = -cxy * inv;
        float hC =  0.5f * cxx * inv;
        float smax = __logf(255.0f * op);   // alpha>=1/255 <=> sigma<=smax

        bool keep = false;
        if (det > 0.0f && smax > 0.0f) {
            float rx = sqrtf(2.0f * smax * cxx) * 1.001f + 0.02f;
            float ry = sqrtf(2.0f * smax * cyy) * 1.001f + 0.02f;
            keep = (gx + rx >= txmin) && (gx - rx <= txmax) &&
                   (gy + ry >= tymin) && (gy - ry <= tymax);
        }

        // ---- deterministic ballot compaction (double-buffered) ----
        unsigned mask = __ballot_sync(0xffffffffu, keep);
        if (lane == 0) swc[c][wid] = __popc(mask);
        __syncthreads();                       // swc visible
        int bp = 0, total = 0;
        #pragma unroll
        for (int w = 0; w < 8; w++) {
            int cw = swc[c][w];
            bp += (w < wid) ? cw : 0;
            total += cw;
        }
        if (keep) {
            int pos = bp + __popc(mask & ((1u << lane) - 1u));
            sA[c][pos]  = make_float4(gx, gy, hA, Bc);
            sB[c][pos]  = make_float4(hC, op, f0, f1);
            scb[c][pos] = f2;
        }
        __syncthreads();                       // compact visible

        // ---- raster accumulate (no trailing barrier: next chunk
        //      writes the other buffer; reuse guarded by its barriers)
        #pragma unroll 2
        for (int j = 0; j < total; j++) {
            float4 a4 = sA[c][j];
            float4 b4 = sB[c][j];
            float  cb = scb[c][j];
            float dx = a4.x - px;
            float dy = a4.y - py;
            float sig = a4.z * dx * dx + a4.w * dx * dy + b4.x * dy * dy;
            float al = fminf(0.999f, b4.y * __expf(-sig));
            al = (sig >= 0.0f && al >= (1.0f / 255.0f)) ? al : 0.0f;
            accr = fmaf(al, b4.z, accr);
            accg = fmaf(al, b4.w, accg);
            accb = fmaf(al, cb,   accb);
        }
    }

    const int p = (y0 + ty) * WW + (x0 + tx);
    g_imr[p] = fminf(1.0f, fmaxf(0.0f, accr));
    g_img[p] = fminf(1.0f, fmaxf(0.0f, accg));
    g_imb[p] = fminf(1.0f, fmaxf(0.0f, accb));
}

// ============================================================
// K2: up-projection + transposed write, f32x2 packed math.
// Block = (1024 px) x (32 dims); grid (16,24)=384 blocks ->
// SINGLE WAVE (<=3 CTA/SM). 32 independent STG.128 per thread.
// ============================================================
#define D_BLK 32
__global__ __launch_bounds__(256) void k_up(const float* __restrict__ w_up,
                                            const float* __restrict__ b_up,
                                            float* __restrict__ out) {
    // pre-packed duplicated weights: [d][0]={wr2,wg2}, [d][1]={wb2,bias2}
    __shared__ __align__(16) ulonglong2 sw2[D_BLK][2];

    const int tid = threadIdx.x;                   // 256
    const int db  = blockIdx.y * D_BLK;
    if (tid < D_BLK) {
        int d = db + tid;
        float wr = w_up[3*d + 0], wg = w_up[3*d + 1], wb = w_up[3*d + 2];
        float bi = b_up[d];
        ulonglong2 a; a.x = pk2(wr, wr); a.y = pk2(wg, wg);
        ulonglong2 b; b.x = pk2(wb, wb); b.y = pk2(bi, bi);
        sw2[tid][0] = a;
        sw2[tid][1] = b;
    }

    const int p4 = blockIdx.x * 256 + tid;         // float4 pixel index
    float4 R = ((const float4*)g_imr)[p4];
    float4 G = ((const float4*)g_img)[p4];
    float4 B = ((const float4*)g_imb)[p4];
    unsigned long long r01 = pk2(R.x, R.y), r23 = pk2(R.z, R.w);
    unsigned long long g01 = pk2(G.x, G.y), g23 = pk2(G.z, G.w);
    unsigned long long b01 = pk2(B.x, B.y), b23 = pk2(B.z, B.w);
    __syncthreads();

    float* outp = out + (size_t)db * PTOT + (size_t)p4 * 4;
    #pragma unroll 8
    for (int i = 0; i < D_BLK; i++) {
        ulonglong2 wa = sw2[i][0];     // {wr2, wg2}
        ulonglong2 wb = sw2[i][1];     // {wb2, bias2}
        ulonglong2 v;
        v.x = ffma2(b01, wb.x, ffma2(g01, wa.y, ffma2(r01, wa.x, wb.y)));
        v.y = ffma2(b23, wb.x, ffma2(g23, wa.y, ffma2(r23, wa.x, wb.y)));
        *(ulonglong2*)outp = v;
        outp += PTOT;
    }
}

// ============================================================
extern "C" void kernel_launch(void* const* d_in, const int* in_sizes, int n_in,
                              void* d_out, int out_size) {
    // metadata order: x, xyz, scaling, rotation, features, opacity, w_up, b_up
    const float* xyz      = (const float*)d_in[1];
    const float* scaling  = (const float*)d_in[2];
    const float* rotation = (const float*)d_in[3];
    const float* features = (const float*)d_in[4];
    const float* opacity  = (const float*)d_in[5];
    const float* w_up     = (const float*)d_in[6];
    const float* b_up     = (const float*)d_in[7];
    float* out = (float*)d_out;

    k_praster<<<64, 256>>>(xyz, scaling, rotation, features, opacity);
    k_up<<<dim3(PTOT / 1024, DIMU / D_BLK), 256>>>(w_up, b_up, out);
}

// round 7
// speedup vs baseline: 2.0585x; 1.0970x over previous
#include <cuda_runtime.h>

#define WW 128
#define HH 128
#define NP 2048
#define DIMU 768
#define PTOT (HH*WW)

// ---- scratch (device globals: no allocation allowed) ----
__device__ __align__(16) float g_imr[PTOT];
__device__ __align__(16) float g_img[PTOT];
__device__ __align__(16) float g_imb[PTOT];

// ---- packed f32x2 helpers (sm_103a FFMA2) ----
__device__ __forceinline__ unsigned long long pk2(float lo, float hi) {
    unsigned long long v;
    asm("mov.b64 %0, {%1, %2};" : "=l"(v) : "f"(lo), "f"(hi));
    return v;
}
__device__ __forceinline__ unsigned long long ffma2(unsigned long long a,
                                                    unsigned long long b,
                                                    unsigned long long c) {
    unsigned long long d;
    asm("fma.rn.f32x2 %0, %1, %2, %3;" : "=l"(d) : "l"(a), "l"(b), "l"(c));
    return d;
}

// ============================================================
// K1: fused preprocess + tiled rasterizer.
// 128 blocks (8x16 grid of 16x8-px tiles), 256 threads.
// All threads preprocess+cull a 256-gaussian chunk; threads
// 0..127 own one pixel each for the accumulate loop.
// ============================================================
__global__ __launch_bounds__(256, 1) void k_praster(
    const float* __restrict__ xyz, const float* __restrict__ scaling,
    const float* __restrict__ rotation, const float* __restrict__ features,
    const float* __restrict__ opacity)
{
    __shared__ __align__(16) float4 sA[2][256];   // gx, gy, 0.5A, B
    __shared__ __align__(16) float4 sB[2][256];   // 0.5C, op, cr, cg
    __shared__ __align__(16) float  scb[2][256];  // cb
    __shared__ int swc[2][8];

    const int tid  = threadIdx.x;
    const int lane = tid & 31;
    const int wid  = tid >> 5;

    // 8 tiles across (16 px), 16 tiles down (8 px)
    const int x0 = (blockIdx.x & 7) << 4;
    const int y0 = (blockIdx.x >> 3) << 3;
    const int tx = tid & 15, ty = (tid >> 4) & 7;     // pixel for tid<128
    const float px = (float)(x0 + tx) + 0.5f;
    const float py = (float)(y0 + ty) + 0.5f;
    const float txmin = (float)x0 + 0.5f, txmax = (float)x0 + 15.5f;
    const float tymin = (float)y0 + 0.5f, tymax = (float)y0 + 7.5f;
    const bool rasterer = (tid < 128);

    float accr = 0.0f, accg = 0.0f, accb = 0.0f;

    // ---- prefetch chunk 0 ----
    float2 nxy = ((const float2*)xyz)[tid];
    float2 nsc = ((const float2*)scaling)[tid];
    float  nrt = rotation[tid];
    float  nop = opacity[tid];
    float  nf0 = features[3*tid + 0];
    float  nf1 = features[3*tid + 1];
    float  nf2 = features[3*tid + 2];

    #pragma unroll 1
    for (int ck = 0; ck < NP / 256; ck++) {
        const int c = ck & 1;
        float2 xy = nxy; float2 sc = nsc;
        float rt = nrt, op = nop, f0 = nf0, f1 = nf1, f2 = nf2;
        if (ck + 1 < NP / 256) {
            const int ngi = (ck + 1) * 256 + tid;
            nxy = ((const float2*)xyz)[ngi];
            nsc = ((const float2*)scaling)[ngi];
            nrt = rotation[ngi];
            nop = opacity[ngi];
            nf0 = features[3*ngi + 0];
            nf1 = features[3*ngi + 1];
            nf2 = features[3*ngi + 2];
        }

        // ---- preprocess (fast intrinsics) ----
        float e0 = __expf(2.0f * xy.x);
        float e1 = __expf(2.0f * xy.y);
        float gx = __fdividef(128.0f * e0, e0 + 1.0f);   // 0.5*(tanh+1)*W
        float gy = __fdividef(128.0f * e1, e1 + 1.0f);
        float s0 = fabsf(sc.x + 0.5f);
        float s1 = fabsf(sc.y + 0.5f);
        float th = 6.283185307179586f *
                   __fdividef(1.0f, 1.0f + __expf(-rt));
        float sn, cs; __sincosf(th, &sn, &cs);
        float a = cs * s0, b = -sn * s1, dd = sn * s0, ee = cs * s1;
        float cxx = a*a + b*b;
        float cxy = a*dd + b*ee;
        float cyy = dd*dd + ee*ee;
        float det = cxx*cyy - cxy*cxy;
        float inv = __fdividef(1.0f, det);
        float hA =  0.5f * cyy * inv;
        float Bc = -cxy * inv;
        float hC =  0.5f * cxx * inv;
        float smax = __logf(255.0f * op);   // alpha>=1/255 <=> sigma<=smax

        bool keep = false;
        if (det > 0.0f && smax > 0.0f) {
            float rx = sqrtf(2.0f * smax * cxx) * 1.001f + 0.02f;
            float ry = sqrtf(2.0f * smax * cyy) * 1.001f + 0.02f;
            keep = (gx + rx >= txmin) && (gx - rx <= txmax) &&
                   (gy + ry >= tymin) && (gy - ry <= tymax);
        }

        // ---- deterministic ballot compaction (double-buffered) ----
        unsigned mask = __ballot_sync(0xffffffffu, keep);
        if (lane == 0) swc[c][wid] = __popc(mask);
        __syncthreads();
        int bp = 0, total = 0;
        #pragma unroll
        for (int w = 0; w < 8; w++) {
            int cw = swc[c][w];
            bp += (w < wid) ? cw : 0;
            total += cw;
        }
        if (keep) {
            int pos = bp + __popc(mask & ((1u << lane) - 1u));
            sA[c][pos]  = make_float4(gx, gy, hA, Bc);
            sB[c][pos]  = make_float4(hC, op, f0, f1);
            scb[c][pos] = f2;
        }
        __syncthreads();

        // ---- raster accumulate (pixel-owning threads only) ----
        if (rasterer) {
            #pragma unroll 2
            for (int j = 0; j < total; j++) {
                float4 a4 = sA[c][j];
                float4 b4 = sB[c][j];
                float  cb = scb[c][j];
                float dx = a4.x - px;
                float dy = a4.y - py;
                float sig = a4.z * dx * dx + a4.w * dx * dy + b4.x * dy * dy;
                float al = fminf(0.999f, b4.y * __expf(-sig));
                al = (sig >= 0.0f && al >= (1.0f / 255.0f)) ? al : 0.0f;
                accr = fmaf(al, b4.z, accr);
                accg = fmaf(al, b4.w, accg);
                accb = fmaf(al, cb,   accb);
            }
        }
    }

    if (rasterer) {
        const int p = (y0 + ty) * WW + (x0 + tx);
        g_imr[p] = fminf(1.0f, fmaxf(0.0f, accr));
        g_img[p] = fminf(1.0f, fmaxf(0.0f, accg));
        g_imb[p] = fminf(1.0f, fmaxf(0.0f, accb));
    }
}

// ============================================================
// K2: up-projection + transposed write, f32x2 packed math.
// Block = (1024 px) x (16 dims); 768 blocks (single wave,
// ~5.2 CTA/SM). Stores via st.global.cg (bypass L1 queue).
// Weight LDS software-pipelined one dim ahead.
// ============================================================
#define D_BLK 16
__global__ __launch_bounds__(256) void k_up(const float* __restrict__ w_up,
                                            const float* __restrict__ b_up,
                                            float* __restrict__ out) {
    // pre-packed duplicated weights: [d][0]={wr2,wg2}, [d][1]={wb2,bias2}
    __shared__ __align__(16) ulonglong2 sw2[D_BLK][2];

    const int tid = threadIdx.x;                   // 256
    const int db  = blockIdx.y * D_BLK;
    if (tid < D_BLK) {
        int d = db + tid;
        float wr = w_up[3*d + 0], wg = w_up[3*d + 1], wb = w_up[3*d + 2];
        float bi = b_up[d];
        ulonglong2 a; a.x = pk2(wr, wr); a.y = pk2(wg, wg);
        ulonglong2 b; b.x = pk2(wb, wb); b.y = pk2(bi, bi);
        sw2[tid][0] = a;
        sw2[tid][1] = b;
    }

    const int p4 = blockIdx.x * 256 + tid;         // float4 pixel index
    float4 R = ((const float4*)g_imr)[p4];
    float4 G = ((const float4*)g_img)[p4];
    float4 B = ((const float4*)g_imb)[p4];
    unsigned long long r01 = pk2(R.x, R.y), r23 = pk2(R.z, R.w);
    unsigned long long g01 = pk2(G.x, G.y), g23 = pk2(G.z, G.w);
    unsigned long long b01 = pk2(B.x, B.y), b23 = pk2(B.z, B.w);
    __syncthreads();

    float* outp = out + (size_t)db * PTOT + (size_t)p4 * 4;

    // software-pipelined weight fetch
    ulonglong2 wa = sw2[0][0];
    ulonglong2 wb = sw2[0][1];
    #pragma unroll
    for (int i = 0; i < D_BLK; i++) {
        ulonglong2 cwa = wa, cwb = wb;
        if (i + 1 < D_BLK) { wa = sw2[i + 1][0]; wb = sw2[i + 1][1]; }
        float4 v;
        unsigned long long vx =
            ffma2(b01, cwb.x, ffma2(g01, cwa.y, ffma2(r01, cwa.x, cwb.y)));
        unsigned long long vy =
            ffma2(b23, cwb.x, ffma2(g23, cwa.y, ffma2(r23, cwa.x, cwb.y)));
        asm("mov.b64 {%0, %1}, %2;" : "=f"(v.x), "=f"(v.y) : "l"(vx));
        asm("mov.b64 {%0, %1}, %2;" : "=f"(v.z), "=f"(v.w) : "l"(vy));
        __stcg((float4*)outp, v);
        outp += PTOT;
    }
}

// ============================================================
extern "C" void kernel_launch(void* const* d_in, const int* in_sizes, int n_in,
                              void* d_out, int out_size) {
    // metadata order: x, xyz, scaling, rotation, features, opacity, w_up, b_up
    const float* xyz      = (const float*)d_in[1];
    const float* scaling  = (const float*)d_in[2];
    const float* rotation = (const float*)d_in[3];
    const float* features = (const float*)d_in[4];
    const float* opacity  = (const float*)d_in[5];
    const float* w_up     = (const float*)d_in[6];
    const float* b_up     = (const float*)d_in[7];
    float* out = (float*)d_out;

    k_praster<<<128, 256>>>(xyz, scaling, rotation, features, opacity);
    k_up<<<dim3(PTOT / 1024, DIMU / D_BLK), 256>>>(w_up, b_up, out);
}